// round 1
// baseline (speedup 1.0000x reference)
#include <cuda_runtime.h>
#include <math.h>

#define SEQ   2048
#define HID   1024
#define NH    16
#define NKV   4
#define DH    64
#define WIN   64

// Scratch (device globals — no allocation allowed)
__device__ float g_q[SEQ * HID];
__device__ float g_k[SEQ * NKV * DH];
__device__ float g_v[SEQ * NKV * DH];
__device__ float g_attn[SEQ * HID];

// ---------------------------------------------------------------------------
// Generic fp32 GEMM: C[M,N] = A[M,K] @ B[K,N], row-major.
// BM=64, BN=64, BK=16, 256 threads, 4x4 register tile per thread.
// M, N multiples of 64; K multiple of 16 (true for all 4 uses here).
// ---------------------------------------------------------------------------
__global__ __launch_bounds__(256) void gemm64(const float* __restrict__ A,
                                              const float* __restrict__ B,
                                              float* __restrict__ C,
                                              int N, int K) {
    __shared__ float As[16][68];   // As[k][m], padded to dodge store conflicts
    __shared__ float Bs[16][64];   // Bs[k][n]

    const int tid = threadIdx.x;
    const int tx = tid & 15;       // n-dim thread coord
    const int ty = tid >> 4;       // m-dim thread coord
    const int m0 = blockIdx.x * 64;
    const int n0 = blockIdx.y * 64;

    // global load assignments
    const int ar = tid >> 2;          // 0..63 (m within tile)
    const int ac = (tid & 3) * 4;     // 0,4,8,12 (k within tile)
    const int br = tid >> 4;          // 0..15 (k within tile)
    const int bc = (tid & 15) * 4;    // 0..60 (n within tile)

    float acc[4][4] = {};

    for (int k0 = 0; k0 < K; k0 += 16) {
        float4 av = *(const float4*)(A + (size_t)(m0 + ar) * K + k0 + ac);
        float4 bv = *(const float4*)(B + (size_t)(k0 + br) * N + n0 + bc);
        As[ac + 0][ar] = av.x;
        As[ac + 1][ar] = av.y;
        As[ac + 2][ar] = av.z;
        As[ac + 3][ar] = av.w;
        *(float4*)&Bs[br][bc] = bv;
        __syncthreads();

        #pragma unroll
        for (int kk = 0; kk < 16; kk++) {
            float4 a = *(const float4*)&As[kk][ty * 4];
            float4 b = *(const float4*)&Bs[kk][tx * 4];
            acc[0][0] += a.x * b.x; acc[0][1] += a.x * b.y;
            acc[0][2] += a.x * b.z; acc[0][3] += a.x * b.w;
            acc[1][0] += a.y * b.x; acc[1][1] += a.y * b.y;
            acc[1][2] += a.y * b.z; acc[1][3] += a.y * b.w;
            acc[2][0] += a.z * b.x; acc[2][1] += a.z * b.y;
            acc[2][2] += a.z * b.z; acc[2][3] += a.z * b.w;
            acc[3][0] += a.w * b.x; acc[3][1] += a.w * b.y;
            acc[3][2] += a.w * b.z; acc[3][3] += a.w * b.w;
        }
        __syncthreads();
    }

    #pragma unroll
    for (int i = 0; i < 4; i++) {
        float4 o = make_float4(acc[i][0], acc[i][1], acc[i][2], acc[i][3]);
        *(float4*)(C + (size_t)(m0 + ty * 4 + i) * N + n0 + tx * 4) = o;
    }
}

// ---------------------------------------------------------------------------
// RoPE in-place on g_q and g_k. One thread per (row, head, i<32) pair.
// Double-precision angle math to match the numpy sincos table closely.
// ---------------------------------------------------------------------------
__global__ void rope_kernel(const int* __restrict__ pos_ids) {
    int idx = blockIdx.x * blockDim.x + threadIdx.x;
    const int QP = SEQ * NH * 32;
    const int KP = SEQ * NKV * 32;
    float* base;
    int i, pos;
    if (idx < QP) {
        i = idx & 31;
        int h = (idx >> 5) & (NH - 1);
        int s = idx >> 9;               // /(32*16)
        base = g_q + (size_t)s * HID + h * DH;
        pos = pos_ids[s];
    } else if (idx < QP + KP) {
        idx -= QP;
        i = idx & 31;
        int h = (idx >> 5) & (NKV - 1);
        int s = idx >> 7;               // /(32*4)
        base = g_k + (size_t)s * (NKV * DH) + h * DH;
        pos = pos_ids[s];
    } else {
        return;
    }
    double invf = pow(10000.0, -(double)i / 32.0);
    float ang = (float)((double)pos * invf);   // reference rounds freqs to f32
    float c = (float)cos((double)ang);
    float sn = (float)sin((double)ang);
    float x0 = base[i];
    float x1 = base[i + 32];
    base[i]      = x0 * c - x1 * sn;
    base[i + 32] = x1 * c + x0 * sn;
}

// ---------------------------------------------------------------------------
// Sliding-window attention. One block per (32-query tile, kv head).
// Window: query s attends positions s-63..s (left pad -> score 0, still in
// the softmax, matching the reference's zero-padded k/v with all-ones mask).
// ---------------------------------------------------------------------------
__global__ __launch_bounds__(256) void attn_kernel(const int* __restrict__ mask) {
    extern __shared__ float sm[];
    // kT: [64 d][97 stride] covering 95 kv rows   (6208 floats)
    // vS: [95 rows][64 d]                          (6080 floats)
    // qs: [128 rows][64 d]                         (8192 floats)
    // ps: [8 warps][64 w]                          (512 floats)
    float* kT = sm;
    float* vS = kT + 64 * 97;
    float* qs = vS + 95 * 64;
    float* ps = qs + 128 * 64;

    const int g  = blockIdx.y;            // kv head
    const int s0 = blockIdx.x * 32;       // first query in tile
    const int tid = threadIdx.x;

    // Stage K and V rows [s0-63 .. s0+31] (95 rows), zero for negative rows.
    for (int idx = tid; idx < 95 * 64; idx += 256) {
        int j = idx >> 6;
        int d = idx & 63;
        int jg = s0 - 63 + j;
        float kv = 0.f, vv = 0.f;
        if (jg >= 0) {
            size_t off = (size_t)jg * (NKV * DH) + g * DH + d;
            kv = g_k[off];
            vv = g_v[off];
        }
        kT[d * 97 + j] = kv;   // stride 97 -> conflict-free transposed store
        vS[idx] = vv;
    }
    // Stage Q: 32 queries x 4 heads of this group. row r = sl*4 + hl.
    for (int idx = tid; idx < 128 * 64; idx += 256) {
        int r = idx >> 6;
        int d = idx & 63;
        int sl = r >> 2;
        int hl = r & 3;
        qs[idx] = g_q[(size_t)(s0 + sl) * HID + (4 * g + hl) * DH + d];
    }
    __syncthreads();

    const int warp = tid >> 5;
    const int lane = tid & 31;
    float* pw_row = ps + warp * 64;

    for (int it = 0; it < 16; it++) {
        int r  = warp * 16 + it;
        int sl = r >> 2;
        int hl = r & 3;
        int s  = s0 + sl;
        int jb = sl;                       // kv row for window pos w is jb + w

        // scores: lane owns window positions (lane, lane+32)
        const float* qrow = qs + r * 64;
        float sc0 = 0.f, sc1 = 0.f;
        #pragma unroll
        for (int d = 0; d < 64; d++) {
            float qd = qrow[d];                       // broadcast
            const float* kr = kT + d * 97 + jb;
            sc0 += qd * kr[lane];
            sc1 += qd * kr[lane + 32];
        }
        sc0 *= 0.125f;
        sc1 *= 0.125f;

        const int* mrow = mask + (size_t)s * WIN;
        if (mrow[lane]      <= 0) sc0 = -1e30f;
        if (mrow[lane + 32] <= 0) sc1 = -1e30f;

        // softmax over 64 window positions (2 per lane)
        float mx = fmaxf(sc0, sc1);
        #pragma unroll
        for (int o = 16; o; o >>= 1) mx = fmaxf(mx, __shfl_xor_sync(0xffffffffu, mx, o));
        float e0 = __expf(sc0 - mx);
        float e1 = __expf(sc1 - mx);
        float sum = e0 + e1;
        #pragma unroll
        for (int o = 16; o; o >>= 1) sum += __shfl_xor_sync(0xffffffffu, sum, o);
        float inv = 1.f / sum;

        pw_row[lane]      = e0 * inv;
        pw_row[lane + 32] = e1 * inv;
        __syncwarp();

        // PV: lane owns dims (2*lane, 2*lane+1)
        float o0 = 0.f, o1 = 0.f;
        int d0 = lane * 2;
        #pragma unroll
        for (int w = 0; w < 64; w++) {
            float p = pw_row[w];                      // broadcast
            float2 vv = *(const float2*)&vS[(jb + w) * 64 + d0];
            o0 += p * vv.x;
            o1 += p * vv.y;
        }
        __syncwarp();

        float* op = g_attn + (size_t)s * HID + (4 * g + hl) * DH + d0;
        *(float2*)op = make_float2(o0, o1);
    }
}

// ---------------------------------------------------------------------------
extern "C" void kernel_launch(void* const* d_in, const int* in_sizes, int n_in,
                              void* d_out, int out_size) {
    const float* hidden = (const float*)d_in[0];
    const int*   mask   = (const int*)d_in[1];
    const int*   pos    = (const int*)d_in[2];
    const float* qw     = (const float*)d_in[3];
    const float* kw     = (const float*)d_in[4];
    const float* vw     = (const float*)d_in[5];
    const float* ow     = (const float*)d_in[6];
    float* out = (float*)d_out;

    float *dq, *dk, *dv, *dattn;
    cudaGetSymbolAddress((void**)&dq, g_q);
    cudaGetSymbolAddress((void**)&dk, g_k);
    cudaGetSymbolAddress((void**)&dv, g_v);
    cudaGetSymbolAddress((void**)&dattn, g_attn);

    const int ATTN_SMEM = (64 * 97 + 95 * 64 + 128 * 64 + 8 * 64) * 4; // 83968
    cudaFuncSetAttribute(attn_kernel,
                         cudaFuncAttributeMaxDynamicSharedMemorySize, ATTN_SMEM);

    dim3 gq(SEQ / 64, HID / 64);          // (32, 16)
    dim3 gkv(SEQ / 64, (NKV * DH) / 64);  // (32, 4)

    gemm64<<<gq, 256>>>(hidden, qw, dq, HID, HID);
    gemm64<<<gkv, 256>>>(hidden, kw, dk, NKV * DH, HID);
    gemm64<<<gkv, 256>>>(hidden, vw, dv, NKV * DH, HID);

    int rope_total = SEQ * NH * 32 + SEQ * NKV * 32;
    rope_kernel<<<(rope_total + 255) / 256, 256>>>(pos);

    dim3 ga(SEQ / 32, NKV);               // (64, 4)
    attn_kernel<<<ga, 256, ATTN_SMEM>>>(mask);

    gemm64<<<gq, 256>>>(dattn, ow, out, HID, HID);
}

// round 2
// speedup vs baseline: 1.6828x; 1.6828x over previous
#include <cuda_runtime.h>
#include <math.h>

#define SEQ   2048
#define HID   1024
#define NH    16
#define NKV   4
#define DH    64
#define WIN   64

// Scratch (device globals — no allocation allowed)
__device__ float g_q[SEQ * HID];
__device__ float g_k[SEQ * NKV * DH];
__device__ float g_v[SEQ * NKV * DH];
__device__ float g_attn[SEQ * HID];
__device__ float2 g_sc[SEQ * 32];      // per (row, i<32): (sin, cos)

// ---------------------------------------------------------------------------
// Packed f32x2 helpers (sm_103a FFMA2 — PTX only)
// ---------------------------------------------------------------------------
typedef unsigned long long u64;
__device__ __forceinline__ u64 pack2(float x, float y) {
    u64 r; asm("mov.b64 %0, {%1, %2};" : "=l"(r) : "f"(x), "f"(y)); return r;
}
__device__ __forceinline__ void fma2(u64& d, u64 a, u64 b) {
    asm("fma.rn.f32x2 %0, %1, %2, %0;" : "+l"(d) : "l"(a), "l"(b));
}
__device__ __forceinline__ float2 unpack2(u64 v) {
    float2 r; asm("mov.b64 {%0, %1}, %2;" : "=f"(r.x), "=f"(r.y) : "l"(v)); return r;
}

// ---------------------------------------------------------------------------
// Generic fp32 GEMM: C[M,N] = A[M,K] @ B[K,N], row-major, FFMA2 inner loop.
// BM=64, BN=64, BK=16, 256 threads, 4x4 register tile per thread.
// ---------------------------------------------------------------------------
__global__ __launch_bounds__(256) void gemm64(const float* __restrict__ A,
                                              const float* __restrict__ B,
                                              float* __restrict__ C,
                                              int N, int K) {
    __shared__ float As[16][68];   // As[k][m], padded
    __shared__ float Bs[16][64];   // Bs[k][n]

    const int tid = threadIdx.x;
    const int tx = tid & 15;       // n-dim thread coord
    const int ty = tid >> 4;       // m-dim thread coord
    const int m0 = blockIdx.x * 64;
    const int n0 = blockIdx.y * 64;

    const int ar = tid >> 2;          // 0..63 (m within tile)
    const int ac = (tid & 3) * 4;     // 0,4,8,12 (k within tile)
    const int br = tid >> 4;          // 0..15 (k within tile)
    const int bc = (tid & 15) * 4;    // 0..60 (n within tile)

    // acc2[p][j]: packed pair of m-rows (ty*4 + 2p, ty*4 + 2p + 1), col tx*4+j
    u64 acc2[2][4] = {};

    for (int k0 = 0; k0 < K; k0 += 16) {
        float4 av = *(const float4*)(A + (size_t)(m0 + ar) * K + k0 + ac);
        float4 bv = *(const float4*)(B + (size_t)(k0 + br) * N + n0 + bc);
        As[ac + 0][ar] = av.x;
        As[ac + 1][ar] = av.y;
        As[ac + 2][ar] = av.z;
        As[ac + 3][ar] = av.w;
        *(float4*)&Bs[br][bc] = bv;
        __syncthreads();

        #pragma unroll
        for (int kk = 0; kk < 16; kk++) {
            ulonglong2 ap = *(const ulonglong2*)&As[kk][ty * 4];  // (m0,m1),(m2,m3)
            float4 b = *(const float4*)&Bs[kk][tx * 4];
            u64 b0 = pack2(b.x, b.x);
            u64 b1 = pack2(b.y, b.y);
            u64 b2 = pack2(b.z, b.z);
            u64 b3 = pack2(b.w, b.w);
            fma2(acc2[0][0], ap.x, b0); fma2(acc2[0][1], ap.x, b1);
            fma2(acc2[0][2], ap.x, b2); fma2(acc2[0][3], ap.x, b3);
            fma2(acc2[1][0], ap.y, b0); fma2(acc2[1][1], ap.y, b1);
            fma2(acc2[1][2], ap.y, b2); fma2(acc2[1][3], ap.y, b3);
        }
        __syncthreads();
    }

    #pragma unroll
    for (int p = 0; p < 2; p++) {
        float2 u0 = unpack2(acc2[p][0]);
        float2 u1 = unpack2(acc2[p][1]);
        float2 u2 = unpack2(acc2[p][2]);
        float2 u3 = unpack2(acc2[p][3]);
        int r0 = m0 + ty * 4 + 2 * p;
        *(float4*)(C + (size_t)r0 * N + n0 + tx * 4) =
            make_float4(u0.x, u1.x, u2.x, u3.x);
        *(float4*)(C + (size_t)(r0 + 1) * N + n0 + tx * 4) =
            make_float4(u0.y, u1.y, u2.y, u3.y);
    }
}

// ---------------------------------------------------------------------------
// Sincos table: one thread per (row s, i<32). FP64 work done 65K times only.
// ---------------------------------------------------------------------------
__global__ void sincos_table_kernel(const int* __restrict__ pos_ids) {
    int idx = blockIdx.x * blockDim.x + threadIdx.x;
    if (idx >= SEQ * 32) return;
    int i = idx & 31;
    int s = idx >> 5;
    int pos = pos_ids[s];
    double invf = pow(10000.0, -(double)i / 32.0);
    float ang = (float)((double)pos * invf);   // reference rounds freqs to f32
    double sd, cd;
    sincos((double)ang, &sd, &cd);
    g_sc[idx] = make_float2((float)sd, (float)cd);
}

// ---------------------------------------------------------------------------
// RoPE apply (table lookup). One thread per (row, head, i<32) pair.
// ---------------------------------------------------------------------------
__global__ void rope_apply_kernel() {
    int idx = blockIdx.x * blockDim.x + threadIdx.x;
    const int QP = SEQ * NH * 32;
    const int KP = SEQ * NKV * 32;
    float* base;
    int i, s;
    if (idx < QP) {
        i = idx & 31;
        int h = (idx >> 5) & (NH - 1);
        s = idx >> 9;
        base = g_q + (size_t)s * HID + h * DH;
    } else if (idx < QP + KP) {
        idx -= QP;
        i = idx & 31;
        int h = (idx >> 5) & (NKV - 1);
        s = idx >> 7;
        base = g_k + (size_t)s * (NKV * DH) + h * DH;
    } else {
        return;
    }
    float2 sc = g_sc[s * 32 + i];
    float x0 = base[i];
    float x1 = base[i + 32];
    base[i]      = x0 * sc.y - x1 * sc.x;
    base[i + 32] = x1 * sc.y + x0 * sc.x;
}

// ---------------------------------------------------------------------------
// Sliding-window attention. One block per (32-query tile, kv head).
// ---------------------------------------------------------------------------
__global__ __launch_bounds__(256) void attn_kernel(const int* __restrict__ mask) {
    extern __shared__ float sm[];
    float* kT = sm;                 // [64 d][97] covering 95 kv rows
    float* vS = kT + 64 * 97;       // [95][64]
    float* qs = vS + 95 * 64;       // [128][64]
    float* ps = qs + 128 * 64;      // [8 warps][64]

    const int g  = blockIdx.y;
    const int s0 = blockIdx.x * 32;
    const int tid = threadIdx.x;

    for (int idx = tid; idx < 95 * 64; idx += 256) {
        int j = idx >> 6;
        int d = idx & 63;
        int jg = s0 - 63 + j;
        float kv = 0.f, vv = 0.f;
        if (jg >= 0) {
            size_t off = (size_t)jg * (NKV * DH) + g * DH + d;
            kv = g_k[off];
            vv = g_v[off];
        }
        kT[d * 97 + j] = kv;
        vS[idx] = vv;
    }
    for (int idx = tid; idx < 128 * 64; idx += 256) {
        int r = idx >> 6;
        int d = idx & 63;
        int sl = r >> 2;
        int hl = r & 3;
        qs[idx] = g_q[(size_t)(s0 + sl) * HID + (4 * g + hl) * DH + d];
    }
    __syncthreads();

    const int warp = tid >> 5;
    const int lane = tid & 31;
    float* pw_row = ps + warp * 64;

    for (int it = 0; it < 16; it++) {
        int r  = warp * 16 + it;
        int sl = r >> 2;
        int hl = r & 3;
        int s  = s0 + sl;
        int jb = sl;

        const float* qrow = qs + r * 64;
        float sc0 = 0.f, sc1 = 0.f;
        #pragma unroll
        for (int d = 0; d < 64; d++) {
            float qd = qrow[d];
            const float* kr = kT + d * 97 + jb;
            sc0 += qd * kr[lane];
            sc1 += qd * kr[lane + 32];
        }
        sc0 *= 0.125f;
        sc1 *= 0.125f;

        const int* mrow = mask + (size_t)s * WIN;
        if (mrow[lane]      <= 0) sc0 = -1e30f;
        if (mrow[lane + 32] <= 0) sc1 = -1e30f;

        float mx = fmaxf(sc0, sc1);
        #pragma unroll
        for (int o = 16; o; o >>= 1) mx = fmaxf(mx, __shfl_xor_sync(0xffffffffu, mx, o));
        float e0 = __expf(sc0 - mx);
        float e1 = __expf(sc1 - mx);
        float sum = e0 + e1;
        #pragma unroll
        for (int o = 16; o; o >>= 1) sum += __shfl_xor_sync(0xffffffffu, sum, o);
        float inv = 1.f / sum;

        pw_row[lane]      = e0 * inv;
        pw_row[lane + 32] = e1 * inv;
        __syncwarp();

        float o0 = 0.f, o1 = 0.f;
        int d0 = lane * 2;
        #pragma unroll
        for (int w = 0; w < 64; w++) {
            float p = pw_row[w];
            float2 vv = *(const float2*)&vS[(jb + w) * 64 + d0];
            o0 += p * vv.x;
            o1 += p * vv.y;
        }
        __syncwarp();

        float* op = g_attn + (size_t)s * HID + (4 * g + hl) * DH + d0;
        *(float2*)op = make_float2(o0, o1);
    }
}

// ---------------------------------------------------------------------------
extern "C" void kernel_launch(void* const* d_in, const int* in_sizes, int n_in,
                              void* d_out, int out_size) {
    const float* hidden = (const float*)d_in[0];
    const int*   mask   = (const int*)d_in[1];
    const int*   pos    = (const int*)d_in[2];
    const float* qw     = (const float*)d_in[3];
    const float* kw     = (const float*)d_in[4];
    const float* vw     = (const float*)d_in[5];
    const float* ow     = (const float*)d_in[6];
    float* out = (float*)d_out;

    float *dq, *dk, *dv, *dattn;
    cudaGetSymbolAddress((void**)&dq, g_q);
    cudaGetSymbolAddress((void**)&dk, g_k);
    cudaGetSymbolAddress((void**)&dv, g_v);
    cudaGetSymbolAddress((void**)&dattn, g_attn);

    const int ATTN_SMEM = (64 * 97 + 95 * 64 + 128 * 64 + 8 * 64) * 4; // 83968
    cudaFuncSetAttribute(attn_kernel,
                         cudaFuncAttributeMaxDynamicSharedMemorySize, ATTN_SMEM);

    dim3 gq(SEQ / 64, HID / 64);          // (32, 16)
    dim3 gkv(SEQ / 64, (NKV * DH) / 64);  // (32, 4)

    sincos_table_kernel<<<(SEQ * 32 + 255) / 256, 256>>>(pos);

    gemm64<<<gq, 256>>>(hidden, qw, dq, HID, HID);
    gemm64<<<gkv, 256>>>(hidden, kw, dk, NKV * DH, HID);
    gemm64<<<gkv, 256>>>(hidden, vw, dv, NKV * DH, HID);

    int rope_total = SEQ * NH * 32 + SEQ * NKV * 32;
    rope_apply_kernel<<<(rope_total + 255) / 256, 256>>>();

    dim3 ga(SEQ / 32, NKV);               // (64, 4)
    attn_kernel<<<ga, 256, ATTN_SMEM>>>(mask);

    gemm64<<<gq, 256>>>(dattn, ow, out, HID, HID);
}

// round 3
// speedup vs baseline: 2.0973x; 1.2463x over previous
#include <cuda_runtime.h>
#include <math.h>

#define SEQ   2048
#define HID   1024
#define NH    16
#define NKV   4
#define DH    64
#define WIN   64

// Scratch (device globals — no allocation allowed)
__device__ float g_q[SEQ * HID];
__device__ float g_k[SEQ * NKV * DH];
__device__ float g_v[SEQ * NKV * DH];
__device__ float g_attn[SEQ * HID];
__device__ float2 g_sc[SEQ * 32];      // per (row, i<32): (sin, cos)

// ---------------------------------------------------------------------------
// Packed f32x2 helpers (sm_103a FFMA2 — PTX only)
// ---------------------------------------------------------------------------
typedef unsigned long long u64;
__device__ __forceinline__ u64 pack2(float x, float y) {
    u64 r; asm("mov.b64 %0, {%1, %2};" : "=l"(r) : "f"(x), "f"(y)); return r;
}
__device__ __forceinline__ void fma2(u64& d, u64 a, u64 b) {
    asm("fma.rn.f32x2 %0, %1, %2, %0;" : "+l"(d) : "l"(a), "l"(b));
}
__device__ __forceinline__ float2 unpack2(u64 v) {
    float2 r; asm("mov.b64 {%0, %1}, %2;" : "=f"(r.x), "=f"(r.y) : "l"(v)); return r;
}

// ---------------------------------------------------------------------------
// GEMM body: C[m0:m0+128, n0:n0+64] = A[m0:,:K] @ B[:K, n0:]
// BM=128, BN=64, BK=16, 256 threads, 8x4 per-thread tile (f32x2 packed),
// register-prefetch software pipeline over the K loop.
// ---------------------------------------------------------------------------
struct GemmSmem {
    float As[16][132];   // As[k][m], padded (132*4B=528B row, 16B aligned)
    float Bs[16][64];    // Bs[k][n]
};

__device__ __forceinline__ void gemm_body(const float* __restrict__ A,
                                          const float* __restrict__ B,
                                          float* __restrict__ C,
                                          int N, int K, int m0, int n0,
                                          GemmSmem& sm) {
    const int tid = threadIdx.x;
    const int tx = tid & 15;          // n coord
    const int ty = tid >> 4;          // m coord
    const int ar = tid >> 1;          // 0..127 (m within tile)
    const int ac = (tid & 1) * 8;     // 0 or 8 (k within tile)
    const int br = tid >> 4;          // 0..15 (k within tile)
    const int bc = (tid & 15) * 4;    // n within tile

    const float* Ap = A + (size_t)(m0 + ar) * K + ac;
    const float* Bp = B + (size_t)br * N + n0 + bc;

    u64 acc2[4][4] = {};

    float4 pa0 = *(const float4*)(Ap);
    float4 pa1 = *(const float4*)(Ap + 4);
    float4 pb  = *(const float4*)(Bp);

    for (int k0 = 0; k0 < K; k0 += 16) {
        sm.As[ac + 0][ar] = pa0.x;
        sm.As[ac + 1][ar] = pa0.y;
        sm.As[ac + 2][ar] = pa0.z;
        sm.As[ac + 3][ar] = pa0.w;
        sm.As[ac + 4][ar] = pa1.x;
        sm.As[ac + 5][ar] = pa1.y;
        sm.As[ac + 6][ar] = pa1.z;
        sm.As[ac + 7][ar] = pa1.w;
        *(float4*)&sm.Bs[br][bc] = pb;
        __syncthreads();

        if (k0 + 16 < K) {
            pa0 = *(const float4*)(Ap + k0 + 16);
            pa1 = *(const float4*)(Ap + k0 + 20);
            pb  = *(const float4*)(Bp + (size_t)(k0 + 16) * N);
        }

        #pragma unroll
        for (int kk = 0; kk < 16; kk++) {
            ulonglong2 a01 = *(const ulonglong2*)&sm.As[kk][ty * 8];
            ulonglong2 a23 = *(const ulonglong2*)&sm.As[kk][ty * 8 + 4];
            float4 b = *(const float4*)&sm.Bs[kk][tx * 4];
            u64 b0 = pack2(b.x, b.x);
            u64 b1 = pack2(b.y, b.y);
            u64 b2 = pack2(b.z, b.z);
            u64 b3 = pack2(b.w, b.w);
            fma2(acc2[0][0], a01.x, b0); fma2(acc2[0][1], a01.x, b1);
            fma2(acc2[0][2], a01.x, b2); fma2(acc2[0][3], a01.x, b3);
            fma2(acc2[1][0], a01.y, b0); fma2(acc2[1][1], a01.y, b1);
            fma2(acc2[1][2], a01.y, b2); fma2(acc2[1][3], a01.y, b3);
            fma2(acc2[2][0], a23.x, b0); fma2(acc2[2][1], a23.x, b1);
            fma2(acc2[2][2], a23.x, b2); fma2(acc2[2][3], a23.x, b3);
            fma2(acc2[3][0], a23.y, b0); fma2(acc2[3][1], a23.y, b1);
            fma2(acc2[3][2], a23.y, b2); fma2(acc2[3][3], a23.y, b3);
        }
        __syncthreads();
    }

    #pragma unroll
    for (int p = 0; p < 4; p++) {
        float2 u0 = unpack2(acc2[p][0]);
        float2 u1 = unpack2(acc2[p][1]);
        float2 u2 = unpack2(acc2[p][2]);
        float2 u3 = unpack2(acc2[p][3]);
        int r0 = m0 + ty * 8 + 2 * p;
        *(float4*)(C + (size_t)r0 * N + n0 + tx * 4) =
            make_float4(u0.x, u1.x, u2.x, u3.x);
        *(float4*)(C + (size_t)(r0 + 1) * N + n0 + tx * 4) =
            make_float4(u0.y, u1.y, u2.y, u3.y);
    }
}

// Fused QKV projection: n-tile selects which weight/output it belongs to.
__global__ __launch_bounds__(256, 2) void gemm_qkv(const float* __restrict__ hidden,
                                                   const float* __restrict__ qw,
                                                   const float* __restrict__ kw,
                                                   const float* __restrict__ vw) {
    __shared__ GemmSmem sm;
    int nt = blockIdx.y;
    const float* B;
    float* C;
    int N, n0;
    if (nt < 16)      { B = qw; C = g_q; N = HID;      n0 = nt * 64; }
    else if (nt < 20) { B = kw; C = g_k; N = NKV * DH; n0 = (nt - 16) * 64; }
    else              { B = vw; C = g_v; N = NKV * DH; n0 = (nt - 20) * 64; }
    gemm_body(hidden, B, C, N, HID, blockIdx.x * 128, n0, sm);
}

// Plain GEMM (O projection).
__global__ __launch_bounds__(256, 2) void gemm128(const float* __restrict__ A,
                                                  const float* __restrict__ B,
                                                  float* __restrict__ C,
                                                  int N, int K) {
    __shared__ GemmSmem sm;
    gemm_body(A, B, C, N, K, blockIdx.x * 128, blockIdx.y * 64, sm);
}

// ---------------------------------------------------------------------------
// Sincos table: one thread per (row s, i<32). FP64 work done 65K times only.
// ---------------------------------------------------------------------------
__global__ void sincos_table_kernel(const int* __restrict__ pos_ids) {
    int idx = blockIdx.x * blockDim.x + threadIdx.x;
    if (idx >= SEQ * 32) return;
    int i = idx & 31;
    int s = idx >> 5;
    int pos = pos_ids[s];
    double invf = pow(10000.0, -(double)i / 32.0);
    float ang = (float)((double)pos * invf);   // reference rounds freqs to f32
    double sd, cd;
    sincos((double)ang, &sd, &cd);
    g_sc[idx] = make_float2((float)sd, (float)cd);
}

// ---------------------------------------------------------------------------
// RoPE apply (table lookup). One thread per (row, head, i<32) pair.
// ---------------------------------------------------------------------------
__global__ void rope_apply_kernel() {
    int idx = blockIdx.x * blockDim.x + threadIdx.x;
    const int QP = SEQ * NH * 32;
    const int KP = SEQ * NKV * 32;
    float* base;
    int i, s;
    if (idx < QP) {
        i = idx & 31;
        int h = (idx >> 5) & (NH - 1);
        s = idx >> 9;
        base = g_q + (size_t)s * HID + h * DH;
    } else if (idx < QP + KP) {
        idx -= QP;
        i = idx & 31;
        int h = (idx >> 5) & (NKV - 1);
        s = idx >> 7;
        base = g_k + (size_t)s * (NKV * DH) + h * DH;
    } else {
        return;
    }
    float2 sc = g_sc[s * 32 + i];
    float x0 = base[i];
    float x1 = base[i + 32];
    base[i]      = x0 * sc.y - x1 * sc.x;
    base[i + 32] = x1 * sc.y + x0 * sc.x;
}

// ---------------------------------------------------------------------------
// Sliding-window attention. One block per (32-query tile, kv head).
// ---------------------------------------------------------------------------
__global__ __launch_bounds__(256) void attn_kernel(const int* __restrict__ mask) {
    extern __shared__ float smarr[];
    float* kT = smarr;              // [64 d][97] covering 95 kv rows
    float* vS = kT + 64 * 97;       // [95][64]
    float* qs = vS + 95 * 64;       // [128][64]
    float* ps = qs + 128 * 64;      // [8 warps][64]

    const int g  = blockIdx.y;
    const int s0 = blockIdx.x * 32;
    const int tid = threadIdx.x;

    for (int idx = tid; idx < 95 * 64; idx += 256) {
        int j = idx >> 6;
        int d = idx & 63;
        int jg = s0 - 63 + j;
        float kv = 0.f, vv = 0.f;
        if (jg >= 0) {
            size_t off = (size_t)jg * (NKV * DH) + g * DH + d;
            kv = g_k[off];
            vv = g_v[off];
        }
        kT[d * 97 + j] = kv;
        vS[idx] = vv;
    }
    for (int idx = tid; idx < 128 * 64; idx += 256) {
        int r = idx >> 6;
        int d = idx & 63;
        int sl = r >> 2;
        int hl = r & 3;
        qs[idx] = g_q[(size_t)(s0 + sl) * HID + (4 * g + hl) * DH + d];
    }
    __syncthreads();

    const int warp = tid >> 5;
    const int lane = tid & 31;
    float* pw_row = ps + warp * 64;

    for (int it = 0; it < 16; it++) {
        int r  = warp * 16 + it;
        int sl = r >> 2;
        int hl = r & 3;
        int s  = s0 + sl;
        int jb = sl;

        const float* qrow = qs + r * 64;
        float sc0 = 0.f, sc1 = 0.f;
        #pragma unroll
        for (int d = 0; d < 64; d++) {
            float qd = qrow[d];
            const float* kr = kT + d * 97 + jb;
            sc0 += qd * kr[lane];
            sc1 += qd * kr[lane + 32];
        }
        sc0 *= 0.125f;
        sc1 *= 0.125f;

        const int* mrow = mask + (size_t)s * WIN;
        if (mrow[lane]      <= 0) sc0 = -1e30f;
        if (mrow[lane + 32] <= 0) sc1 = -1e30f;

        float mx = fmaxf(sc0, sc1);
        #pragma unroll
        for (int o = 16; o; o >>= 1) mx = fmaxf(mx, __shfl_xor_sync(0xffffffffu, mx, o));
        float e0 = __expf(sc0 - mx);
        float e1 = __expf(sc1 - mx);
        float sum = e0 + e1;
        #pragma unroll
        for (int o = 16; o; o >>= 1) sum += __shfl_xor_sync(0xffffffffu, sum, o);
        float inv = 1.f / sum;

        pw_row[lane]      = e0 * inv;
        pw_row[lane + 32] = e1 * inv;
        __syncwarp();

        float o0 = 0.f, o1 = 0.f;
        int d0 = lane * 2;
        #pragma unroll
        for (int w = 0; w < 64; w++) {
            float p = pw_row[w];
            float2 vv = *(const float2*)&vS[(jb + w) * 64 + d0];
            o0 += p * vv.x;
            o1 += p * vv.y;
        }
        __syncwarp();

        float* op = g_attn + (size_t)s * HID + (4 * g + hl) * DH + d0;
        *(float2*)op = make_float2(o0, o1);
    }
}

// ---------------------------------------------------------------------------
extern "C" void kernel_launch(void* const* d_in, const int* in_sizes, int n_in,
                              void* d_out, int out_size) {
    const float* hidden = (const float*)d_in[0];
    const int*   mask   = (const int*)d_in[1];
    const int*   pos    = (const int*)d_in[2];
    const float* qw     = (const float*)d_in[3];
    const float* kw     = (const float*)d_in[4];
    const float* vw     = (const float*)d_in[5];
    const float* ow     = (const float*)d_in[6];
    float* out = (float*)d_out;

    float *dattn;
    cudaGetSymbolAddress((void**)&dattn, g_attn);

    const int ATTN_SMEM = (64 * 97 + 95 * 64 + 128 * 64 + 8 * 64) * 4; // 83968
    cudaFuncSetAttribute(attn_kernel,
                         cudaFuncAttributeMaxDynamicSharedMemorySize, ATTN_SMEM);

    sincos_table_kernel<<<(SEQ * 32 + 255) / 256, 256>>>(pos);

    dim3 gqkv(SEQ / 128, 24);             // (16, 24) = 384 CTAs
    gemm_qkv<<<gqkv, 256>>>(hidden, qw, kw, vw);

    int rope_total = SEQ * NH * 32 + SEQ * NKV * 32;
    rope_apply_kernel<<<(rope_total + 255) / 256, 256>>>();

    dim3 ga(SEQ / 32, NKV);               // (64, 4)
    attn_kernel<<<ga, 256, ATTN_SMEM>>>(mask);

    dim3 go(SEQ / 128, HID / 64);         // (16, 16) = 256 CTAs
    gemm128<<<go, 256>>>(dattn, ow, out, HID, HID);
}

// round 5
// speedup vs baseline: 3.4334x; 1.6371x over previous
#include <cuda_runtime.h>
#include <cuda_bf16.h>
#include <math.h>
#include <stdint.h>

#define SEQ   2048
#define HID   1024
#define KDIM  1024
#define NH    16
#define NKV   4
#define DH    64
#define WIN   64

// ---------------------------------------------------------------------------
// Scratch (device globals — no allocation allowed)
// ---------------------------------------------------------------------------
__device__ float g_q[SEQ * HID];
__device__ float g_k[SEQ * NKV * DH];
__device__ float g_v[SEQ * NKV * DH];
__device__ float g_attn[SEQ * HID];
__device__ float2 g_sc[SEQ * 32];

__device__ __nv_bfloat16 g_ah[SEQ * KDIM],  g_al[SEQ * KDIM];    // hidden split
__device__ __nv_bfloat16 g_b1h[1536 * KDIM], g_b1l[1536 * KDIM]; // qkv W^T split
__device__ __nv_bfloat16 g_b2h[1024 * KDIM], g_b2l[1024 * KDIM]; // o W^T split
__device__ __nv_bfloat16 g_ch[SEQ * KDIM],  g_cl[SEQ * KDIM];    // attn-out split

// ---------------------------------------------------------------------------
// Baseline-PTX async-copy / ldmatrix / mma helpers (sm_80+, legal in compute_103)
// ---------------------------------------------------------------------------
__device__ __forceinline__ uint32_t smem_u32(const void* p) {
    uint32_t a;
    asm("{ .reg .u64 t; cvta.to.shared.u64 t, %1; cvt.u32.u64 %0, t; }"
        : "=r"(a) : "l"(p));
    return a;
}
__device__ __forceinline__ void cp_async16(uint32_t d, const void* s) {
    asm volatile("cp.async.cg.shared.global [%0], [%1], 16;" :: "r"(d), "l"(s));
}
__device__ __forceinline__ void cp_commit() {
    asm volatile("cp.async.commit_group;" ::: "memory");
}
template <int N> __device__ __forceinline__ void cp_wait() {
    asm volatile("cp.async.wait_group %0;" :: "n"(N) : "memory");
}
__device__ __forceinline__ void ldm_x4(uint32_t* r, uint32_t addr) {
    asm volatile("ldmatrix.sync.aligned.m8n8.x4.shared.b16 {%0,%1,%2,%3}, [%4];"
                 : "=r"(r[0]), "=r"(r[1]), "=r"(r[2]), "=r"(r[3]) : "r"(addr));
}
__device__ __forceinline__ void mma_bf16(float* c, const uint32_t* a,
                                         const uint32_t* b) {
    asm volatile("mma.sync.aligned.m16n8k16.row.col.f32.bf16.bf16.f32 "
                 "{%0,%1,%2,%3}, {%4,%5,%6,%7}, {%8,%9}, {%0,%1,%2,%3};"
                 : "+f"(c[0]), "+f"(c[1]), "+f"(c[2]), "+f"(c[3])
                 : "r"(a[0]), "r"(a[1]), "r"(a[2]), "r"(a[3]),
                   "r"(b[0]), "r"(b[1]));
}

// ---------------------------------------------------------------------------
// Conversion kernels (fp32 -> bf16 hi/lo split)
// ---------------------------------------------------------------------------
__global__ void convert_split(const float* __restrict__ x,
                              __nv_bfloat16* __restrict__ hi,
                              __nv_bfloat16* __restrict__ lo, int n4) {
    int i = blockIdx.x * blockDim.x + threadIdx.x;
    if (i >= n4) return;
    float4 v = ((const float4*)x)[i];
    __nv_bfloat16 h0 = __float2bfloat16_rn(v.x);
    __nv_bfloat16 h1 = __float2bfloat16_rn(v.y);
    __nv_bfloat16 h2 = __float2bfloat16_rn(v.z);
    __nv_bfloat16 h3 = __float2bfloat16_rn(v.w);
    __nv_bfloat16 l0 = __float2bfloat16_rn(v.x - __bfloat162float(h0));
    __nv_bfloat16 l1 = __float2bfloat16_rn(v.y - __bfloat162float(h1));
    __nv_bfloat16 l2 = __float2bfloat16_rn(v.z - __bfloat162float(h2));
    __nv_bfloat16 l3 = __float2bfloat16_rn(v.w - __bfloat162float(h3));
    ((__nv_bfloat162*)hi)[i * 2]     = __nv_bfloat162(h0, h1);
    ((__nv_bfloat162*)hi)[i * 2 + 1] = __nv_bfloat162(h2, h3);
    ((__nv_bfloat162*)lo)[i * 2]     = __nv_bfloat162(l0, l1);
    ((__nv_bfloat162*)lo)[i * 2 + 1] = __nv_bfloat162(l2, l3);
}

// Transpose + split: w[K][Nsrc] -> out[(roff+n)][k] (K-major rows, [N][K])
__global__ void convert_wT(const float* __restrict__ w, int Nsrc, int roff,
                           __nv_bfloat16* __restrict__ th,
                           __nv_bfloat16* __restrict__ tl) {
    __shared__ float t[32][33];
    int nb = blockIdx.x * 32, kb = blockIdx.y * 32;
    int tx = threadIdx.x, ty = threadIdx.y;   // (32, 8)
    #pragma unroll
    for (int j = 0; j < 32; j += 8)
        t[ty + j][tx] = w[(size_t)(kb + ty + j) * Nsrc + nb + tx];
    __syncthreads();
    #pragma unroll
    for (int j = 0; j < 32; j += 8) {
        float x = t[tx][ty + j];
        __nv_bfloat16 h = __float2bfloat16_rn(x);
        __nv_bfloat16 l = __float2bfloat16_rn(x - __bfloat162float(h));
        size_t o = (size_t)(roff + nb + ty + j) * KDIM + kb + tx;
        th[o] = h;
        tl[o] = l;
    }
}

// ---------------------------------------------------------------------------
// HMMA GEMM: C[2048, Ntot] = A @ B^T, bf16-split 3-term, fp32 accum.
// CTA tile 128x128, K chunks of 32, cp.async double buffer, 8 warps (2x4),
// each warp 64x32 via 4x4 m16n8k16 tiles.
// mode 0: qkv demux (blockIdx.y -> g_q/g_k/g_v). mode 1: write Cout.
// ---------------------------------------------------------------------------
#define BK      32
#define ROWB    80                   // smem row: 32 bf16 + 8 pad = 80 bytes
#define MATB    (128 * ROWB)         // 10240 per matrix
#define STAGEB  (4 * MATB)           // Ahi, Alo, Bhi, Blo
#define GSMEM   (2 * STAGEB)         // 81920

__global__ __launch_bounds__(256) void gemm_mma(
    const __nv_bfloat16* __restrict__ Ah, const __nv_bfloat16* __restrict__ Al,
    const __nv_bfloat16* __restrict__ Bh, const __nv_bfloat16* __restrict__ Bl,
    float* __restrict__ Cout, int mode) {
    extern __shared__ char smem[];
    const uint32_t sb = smem_u32(smem);
    const int tid = threadIdx.x;
    const int wid = tid >> 5, lane = tid & 31;
    const int wm = wid >> 2, wn = wid & 3;          // 2 x 4 warp grid
    const int m0 = blockIdx.x * 128;
    const int nt = blockIdx.y;
    const int n0 = nt * 128;

    const __nv_bfloat16* gsrc[4] = {
        Ah + (size_t)m0 * KDIM, Al + (size_t)m0 * KDIM,
        Bh + (size_t)n0 * KDIM, Bl + (size_t)n0 * KDIM };

    const int crow  = tid >> 1;      // 0..127
    const int chalf = tid & 1;       // 16-bf16 half of the 32-wide row

    // ldmatrix lane address components
    const int g    = lane >> 3;               // 0..3 (8x8 block id)
    const int rsub = ((g & 1) << 3) + (lane & 7);   // A: row-in-16
    const int ksubA = (g >> 1) * 8;                 // A: k-in-16
    const int rsubB = ((g >> 1) << 3) + (lane & 7); // B: n-row-in-16
    const int ksubB = (g & 1) * 8;                  // B: k-in-16

    float acc[4][4][4] = {};

    const int NC = KDIM / BK;        // 32
    // prologue
    {
        #pragma unroll
        for (int mat = 0; mat < 4; mat++) {
            const __nv_bfloat16* src = gsrc[mat] + (size_t)crow * KDIM + chalf * 16;
            uint32_t dst = sb + mat * MATB + crow * ROWB + chalf * 32;
            cp_async16(dst, src);
            cp_async16(dst + 16, src + 8);
        }
        cp_commit();
    }

    for (int c = 0; c < NC; c++) {
        const int buf = c & 1;
        if (c + 1 < NC) {
            uint32_t sbase = sb + (buf ^ 1) * STAGEB;
            #pragma unroll
            for (int mat = 0; mat < 4; mat++) {
                const __nv_bfloat16* src =
                    gsrc[mat] + (size_t)crow * KDIM + (c + 1) * BK + chalf * 16;
                uint32_t dst = sbase + mat * MATB + crow * ROWB + chalf * 32;
                cp_async16(dst, src);
                cp_async16(dst + 16, src + 8);
            }
            cp_commit();
            cp_wait<1>();
        } else {
            cp_wait<0>();
        }
        __syncthreads();

        const uint32_t stage = sb + buf * STAGEB;
        #pragma unroll
        for (int ks = 0; ks < 2; ks++) {
            uint32_t afr[4][4], bhf[2][4], blf[2][4];
            // A hi fragments (4 m-tiles)
            #pragma unroll
            for (int mt = 0; mt < 4; mt++)
                ldm_x4(afr[mt], stage + 0 * MATB +
                       (wm * 64 + mt * 16 + rsub) * ROWB + (ks * 16 + ksubA) * 2);
            // B hi fragments (2 pairs of n-tiles)
            #pragma unroll
            for (int p = 0; p < 2; p++)
                ldm_x4(bhf[p], stage + 2 * MATB +
                       (wn * 32 + p * 16 + rsubB) * ROWB + (ks * 16 + ksubB) * 2);
            #pragma unroll
            for (int mt = 0; mt < 4; mt++)
                #pragma unroll
                for (int n4 = 0; n4 < 4; n4++)
                    mma_bf16(acc[mt][n4], afr[mt], &bhf[n4 >> 1][(n4 & 1) * 2]);
            // B lo fragments
            #pragma unroll
            for (int p = 0; p < 2; p++)
                ldm_x4(blf[p], stage + 3 * MATB +
                       (wn * 32 + p * 16 + rsubB) * ROWB + (ks * 16 + ksubB) * 2);
            #pragma unroll
            for (int mt = 0; mt < 4; mt++)
                #pragma unroll
                for (int n4 = 0; n4 < 4; n4++)
                    mma_bf16(acc[mt][n4], afr[mt], &blf[n4 >> 1][(n4 & 1) * 2]);
            // A lo fragments (reuse afr)
            #pragma unroll
            for (int mt = 0; mt < 4; mt++)
                ldm_x4(afr[mt], stage + 1 * MATB +
                       (wm * 64 + mt * 16 + rsub) * ROWB + (ks * 16 + ksubA) * 2);
            #pragma unroll
            for (int mt = 0; mt < 4; mt++)
                #pragma unroll
                for (int n4 = 0; n4 < 4; n4++)
                    mma_bf16(acc[mt][n4], afr[mt], &bhf[n4 >> 1][(n4 & 1) * 2]);
        }
        __syncthreads();
    }

    // epilogue
    float* C;
    int Nc, nc0;
    if (mode == 0) {
        if (nt < 8)       { C = g_q; Nc = HID;      nc0 = n0; }
        else if (nt < 10) { C = g_k; Nc = NKV * DH; nc0 = (nt - 8) * 128; }
        else              { C = g_v; Nc = NKV * DH; nc0 = (nt - 10) * 128; }
    } else { C = Cout; Nc = HID; nc0 = n0; }
    const int rbase = m0 + wm * 64 + (lane >> 2);
    const int cbase = nc0 + wn * 32 + (lane & 3) * 2;
    #pragma unroll
    for (int mt = 0; mt < 4; mt++)
        #pragma unroll
        for (int n4 = 0; n4 < 4; n4++) {
            int r = rbase + mt * 16;
            int cc = cbase + n4 * 8;
            *(float2*)(C + (size_t)r * Nc + cc) =
                make_float2(acc[mt][n4][0], acc[mt][n4][1]);
            *(float2*)(C + (size_t)(r + 8) * Nc + cc) =
                make_float2(acc[mt][n4][2], acc[mt][n4][3]);
        }
}

// ---------------------------------------------------------------------------
// Sincos table + RoPE apply
// ---------------------------------------------------------------------------
__global__ void sincos_table_kernel(const int* __restrict__ pos_ids) {
    int idx = blockIdx.x * blockDim.x + threadIdx.x;
    if (idx >= SEQ * 32) return;
    int i = idx & 31;
    int s = idx >> 5;
    int pos = pos_ids[s];
    double invf = pow(10000.0, -(double)i / 32.0);
    float ang = (float)((double)pos * invf);
    double sd, cd;
    sincos((double)ang, &sd, &cd);
    g_sc[idx] = make_float2((float)sd, (float)cd);
}

__global__ void rope_apply_kernel() {
    int idx = blockIdx.x * blockDim.x + threadIdx.x;
    const int QP = SEQ * NH * 32;
    const int KP = SEQ * NKV * 32;
    float* base;
    int i, s;
    if (idx < QP) {
        i = idx & 31;
        int h = (idx >> 5) & (NH - 1);
        s = idx >> 9;
        base = g_q + (size_t)s * HID + h * DH;
    } else if (idx < QP + KP) {
        idx -= QP;
        i = idx & 31;
        int h = (idx >> 5) & (NKV - 1);
        s = idx >> 7;
        base = g_k + (size_t)s * (NKV * DH) + h * DH;
    } else {
        return;
    }
    float2 sc = g_sc[s * 32 + i];
    float x0 = base[i];
    float x1 = base[i + 32];
    base[i]      = x0 * sc.y - x1 * sc.x;
    base[i + 32] = x1 * sc.y + x0 * sc.x;
}

// ---------------------------------------------------------------------------
// Sliding-window attention: block = (32-query tile, kv head); 4 q-heads per
// kv head share K/V loads inside the warp loop.
// ---------------------------------------------------------------------------
#define ATTN_SMEM ((64 * 97 + 95 * 64 + 128 * 64 + 8 * 4 * 64) * 4)

__global__ __launch_bounds__(256) void attn_kernel(const int* __restrict__ mask) {
    extern __shared__ float smarr[];
    float* kT = smarr;              // [64 d][97]
    float* vS = kT + 64 * 97;       // [95][64]
    float* qs = vS + 95 * 64;       // [128][64]  row r = sl*4 + h
    float* ps = qs + 128 * 64;      // [8 warps][4 h][64]

    const int g  = blockIdx.y;
    const int s0 = blockIdx.x * 32;
    const int tid = threadIdx.x;

    for (int idx = tid; idx < 95 * 64; idx += 256) {
        int j = idx >> 6;
        int d = idx & 63;
        int jg = s0 - 63 + j;
        float kv = 0.f, vv = 0.f;
        if (jg >= 0) {
            size_t off = (size_t)jg * (NKV * DH) + g * DH + d;
            kv = g_k[off];
            vv = g_v[off];
        }
        kT[d * 97 + j] = kv;
        vS[idx] = vv;
    }
    for (int idx = tid; idx < 128 * 64; idx += 256) {
        int r = idx >> 6;
        int d = idx & 63;
        int sl = r >> 2;
        int hl = r & 3;
        qs[idx] = g_q[(size_t)(s0 + sl) * HID + (4 * g + hl) * DH + d];
    }
    __syncthreads();

    const int warp = tid >> 5;
    const int lane = tid & 31;

    for (int sl_i = 0; sl_i < 4; sl_i++) {
        const int sl = warp * 4 + sl_i;
        const int s  = s0 + sl;
        const int jb = sl;

        float sc0[4] = {}, sc1[4] = {};
        #pragma unroll
        for (int d = 0; d < 64; d++) {
            const float* kr = kT + d * 97 + jb;
            float k0 = kr[lane];
            float k1 = kr[lane + 32];
            #pragma unroll
            for (int h = 0; h < 4; h++) {
                float qd = qs[(sl * 4 + h) * 64 + d];
                sc0[h] += qd * k0;
                sc1[h] += qd * k1;
            }
        }
        const int* mrow = mask + (size_t)s * WIN;
        bool mk0 = mrow[lane] <= 0;
        bool mk1 = mrow[lane + 32] <= 0;

        #pragma unroll
        for (int h = 0; h < 4; h++) {
            float a0 = mk0 ? -1e30f : sc0[h] * 0.125f;
            float a1 = mk1 ? -1e30f : sc1[h] * 0.125f;
            float mx = fmaxf(a0, a1);
            #pragma unroll
            for (int o = 16; o; o >>= 1)
                mx = fmaxf(mx, __shfl_xor_sync(0xffffffffu, mx, o));
            float e0 = __expf(a0 - mx);
            float e1 = __expf(a1 - mx);
            float sum = e0 + e1;
            #pragma unroll
            for (int o = 16; o; o >>= 1)
                sum += __shfl_xor_sync(0xffffffffu, sum, o);
            float inv = 1.f / sum;
            float* pr = ps + (warp * 4 + h) * 64;
            pr[lane]      = e0 * inv;
            pr[lane + 32] = e1 * inv;
        }
        __syncwarp();

        float o0[4] = {}, o1[4] = {};
        const int d0 = lane * 2;
        #pragma unroll
        for (int w = 0; w < 64; w++) {
            float2 vv = *(const float2*)&vS[(jb + w) * 64 + d0];
            #pragma unroll
            for (int h = 0; h < 4; h++) {
                float p = ps[(warp * 4 + h) * 64 + w];
                o0[h] += p * vv.x;
                o1[h] += p * vv.y;
            }
        }
        __syncwarp();

        #pragma unroll
        for (int h = 0; h < 4; h++) {
            float* op = g_attn + (size_t)s * HID + (4 * g + h) * DH + d0;
            *(float2*)op = make_float2(o0[h], o1[h]);
        }
    }
}

// ---------------------------------------------------------------------------
extern "C" void kernel_launch(void* const* d_in, const int* in_sizes, int n_in,
                              void* d_out, int out_size) {
    const float* hidden = (const float*)d_in[0];
    const int*   mask   = (const int*)d_in[1];
    const int*   pos    = (const int*)d_in[2];
    const float* qw     = (const float*)d_in[3];
    const float* kw     = (const float*)d_in[4];
    const float* vw     = (const float*)d_in[5];
    const float* ow     = (const float*)d_in[6];
    float* out = (float*)d_out;

    __nv_bfloat16 *ah, *al, *b1h, *b1l, *b2h, *b2l, *chh, *cll;
    float *attn_f;
    cudaGetSymbolAddress((void**)&ah,  g_ah);
    cudaGetSymbolAddress((void**)&al,  g_al);
    cudaGetSymbolAddress((void**)&b1h, g_b1h);
    cudaGetSymbolAddress((void**)&b1l, g_b1l);
    cudaGetSymbolAddress((void**)&b2h, g_b2h);
    cudaGetSymbolAddress((void**)&b2l, g_b2l);
    cudaGetSymbolAddress((void**)&chh, g_ch);
    cudaGetSymbolAddress((void**)&cll, g_cl);
    cudaGetSymbolAddress((void**)&attn_f, g_attn);

    cudaFuncSetAttribute(gemm_mma, cudaFuncAttributeMaxDynamicSharedMemorySize,
                         GSMEM);
    cudaFuncSetAttribute(attn_kernel, cudaFuncAttributeMaxDynamicSharedMemorySize,
                         ATTN_SMEM);

    sincos_table_kernel<<<(SEQ * 32 + 255) / 256, 256>>>(pos);

    convert_split<<<(SEQ * KDIM / 4 + 255) / 256, 256>>>(hidden, ah, al,
                                                         SEQ * KDIM / 4);
    dim3 tb(32, 8);
    convert_wT<<<dim3(HID / 32,      KDIM / 32), tb>>>(qw, HID,      0,    b1h, b1l);
    convert_wT<<<dim3(NKV * DH / 32, KDIM / 32), tb>>>(kw, NKV * DH, 1024, b1h, b1l);
    convert_wT<<<dim3(NKV * DH / 32, KDIM / 32), tb>>>(vw, NKV * DH, 1280, b1h, b1l);
    convert_wT<<<dim3(HID / 32,      KDIM / 32), tb>>>(ow, HID,      0,    b2h, b2l);

    gemm_mma<<<dim3(SEQ / 128, 12), 256, GSMEM>>>(ah, al, b1h, b1l, nullptr, 0);

    int rope_total = SEQ * NH * 32 + SEQ * NKV * 32;
    rope_apply_kernel<<<(rope_total + 255) / 256, 256>>>();

    attn_kernel<<<dim3(SEQ / 32, NKV), 256, ATTN_SMEM>>>(mask);

    convert_split<<<(SEQ * KDIM / 4 + 255) / 256, 256>>>(attn_f, chh, cll,
                                                         SEQ * KDIM / 4);
    gemm_mma<<<dim3(SEQ / 128, 8), 256, GSMEM>>>(chh, cll, b2h, b2l, out, 1);
}

// round 6
// speedup vs baseline: 3.5644x; 1.0382x over previous
#include <cuda_runtime.h>
#include <cuda_bf16.h>
#include <math.h>
#include <stdint.h>

#define SEQ   2048
#define HID   1024
#define KDIM  1024
#define NH    16
#define NKV   4
#define DH    64
#define WIN   64

// ---------------------------------------------------------------------------
// Scratch (device globals — no allocation allowed)
// ---------------------------------------------------------------------------
__device__ float g_q[SEQ * HID];
__device__ float g_k[SEQ * NKV * DH];
__device__ float g_v[SEQ * NKV * DH];
__device__ float2 g_sc[SEQ * 32];

__device__ __nv_bfloat16 g_ah[SEQ * KDIM],  g_al[SEQ * KDIM];    // hidden split
__device__ __nv_bfloat16 g_b1h[1536 * KDIM], g_b1l[1536 * KDIM]; // qkv W^T split
__device__ __nv_bfloat16 g_b2h[1024 * KDIM], g_b2l[1024 * KDIM]; // o W^T split
__device__ __nv_bfloat16 g_ch[SEQ * KDIM],  g_cl[SEQ * KDIM];    // attn-out split

// ---------------------------------------------------------------------------
// Baseline-PTX async-copy / ldmatrix / mma helpers (sm_80+, legal in compute_103)
// ---------------------------------------------------------------------------
__device__ __forceinline__ uint32_t smem_u32(const void* p) {
    uint32_t a;
    asm("{ .reg .u64 t; cvta.to.shared.u64 t, %1; cvt.u32.u64 %0, t; }"
        : "=r"(a) : "l"(p));
    return a;
}
__device__ __forceinline__ void cp_async16(uint32_t d, const void* s) {
    asm volatile("cp.async.cg.shared.global [%0], [%1], 16;" :: "r"(d), "l"(s));
}
__device__ __forceinline__ void cp_commit() {
    asm volatile("cp.async.commit_group;" ::: "memory");
}
template <int N> __device__ __forceinline__ void cp_wait() {
    asm volatile("cp.async.wait_group %0;" :: "n"(N) : "memory");
}
__device__ __forceinline__ void ldm_x4(uint32_t* r, uint32_t addr) {
    asm volatile("ldmatrix.sync.aligned.m8n8.x4.shared.b16 {%0,%1,%2,%3}, [%4];"
                 : "=r"(r[0]), "=r"(r[1]), "=r"(r[2]), "=r"(r[3]) : "r"(addr));
}
__device__ __forceinline__ void mma_bf16(float* c, const uint32_t* a,
                                         const uint32_t* b) {
    asm volatile("mma.sync.aligned.m16n8k16.row.col.f32.bf16.bf16.f32 "
                 "{%0,%1,%2,%3}, {%4,%5,%6,%7}, {%8,%9}, {%0,%1,%2,%3};"
                 : "+f"(c[0]), "+f"(c[1]), "+f"(c[2]), "+f"(c[3])
                 : "r"(a[0]), "r"(a[1]), "r"(a[2]), "r"(a[3]),
                   "r"(b[0]), "r"(b[1]));
}

// ---------------------------------------------------------------------------
// Conversion kernels (fp32 -> bf16 hi/lo split)
// ---------------------------------------------------------------------------
__global__ void convert_split(const float* __restrict__ x,
                              __nv_bfloat16* __restrict__ hi,
                              __nv_bfloat16* __restrict__ lo, int n4) {
    int i = blockIdx.x * blockDim.x + threadIdx.x;
    if (i >= n4) return;
    float4 v = ((const float4*)x)[i];
    __nv_bfloat16 h0 = __float2bfloat16_rn(v.x);
    __nv_bfloat16 h1 = __float2bfloat16_rn(v.y);
    __nv_bfloat16 h2 = __float2bfloat16_rn(v.z);
    __nv_bfloat16 h3 = __float2bfloat16_rn(v.w);
    __nv_bfloat16 l0 = __float2bfloat16_rn(v.x - __bfloat162float(h0));
    __nv_bfloat16 l1 = __float2bfloat16_rn(v.y - __bfloat162float(h1));
    __nv_bfloat16 l2 = __float2bfloat16_rn(v.z - __bfloat162float(h2));
    __nv_bfloat16 l3 = __float2bfloat16_rn(v.w - __bfloat162float(h3));
    ((__nv_bfloat162*)hi)[i * 2]     = __nv_bfloat162(h0, h1);
    ((__nv_bfloat162*)hi)[i * 2 + 1] = __nv_bfloat162(h2, h3);
    ((__nv_bfloat162*)lo)[i * 2]     = __nv_bfloat162(l0, l1);
    ((__nv_bfloat162*)lo)[i * 2 + 1] = __nv_bfloat162(l2, l3);
}

// Merged transpose+split of all 4 weights: w[K][Nsrc] -> dst[(roff+n)][k]
__global__ void convert_wT_all(const float* __restrict__ qw,
                               const float* __restrict__ kw,
                               const float* __restrict__ vw,
                               const float* __restrict__ ow) {
    __shared__ float t[32][33];
    int b = blockIdx.x;
    const float* w;
    __nv_bfloat16 *th, *tl;
    int Nsrc, roff, local;
    if (b < 1024)      { w = qw; th = g_b1h; tl = g_b1l; Nsrc = 1024; roff = 0;    local = b; }
    else if (b < 1280) { w = kw; th = g_b1h; tl = g_b1l; Nsrc = 256;  roff = 1024; local = b - 1024; }
    else if (b < 1536) { w = vw; th = g_b1h; tl = g_b1l; Nsrc = 256;  roff = 1280; local = b - 1280; }
    else               { w = ow; th = g_b2h; tl = g_b2l; Nsrc = 1024; roff = 0;    local = b - 1536; }
    int ntn = Nsrc / 32;
    int nb = (local % ntn) * 32;
    int kb = (local / ntn) * 32;
    int tx = threadIdx.x, ty = threadIdx.y;   // (32, 8)
    #pragma unroll
    for (int j = 0; j < 32; j += 8)
        t[ty + j][tx] = w[(size_t)(kb + ty + j) * Nsrc + nb + tx];
    __syncthreads();
    #pragma unroll
    for (int j = 0; j < 32; j += 8) {
        float x = t[tx][ty + j];
        __nv_bfloat16 h = __float2bfloat16_rn(x);
        __nv_bfloat16 l = __float2bfloat16_rn(x - __bfloat162float(h));
        size_t o = (size_t)(roff + nb + ty + j) * KDIM + kb + tx;
        th[o] = h;
        tl[o] = l;
    }
}

// ---------------------------------------------------------------------------
// HMMA GEMM: C[2048, Ntot] = A @ B^T, bf16-split 3-term, fp32 accum.
// CTA 128x128, K chunks of 32, cp.async double buffer, 8 warps (2x4).
// mode 0: qkv demux (blockIdx.y -> g_q/g_k/g_v). mode 1: write Cout.
// ---------------------------------------------------------------------------
#define BK      32
#define ROWB    80
#define MATB    (128 * ROWB)
#define STAGEB  (4 * MATB)
#define GSMEM   (2 * STAGEB)         // 81920

__global__ __launch_bounds__(256, 2) void gemm_mma(
    const __nv_bfloat16* __restrict__ Ah, const __nv_bfloat16* __restrict__ Al,
    const __nv_bfloat16* __restrict__ Bh, const __nv_bfloat16* __restrict__ Bl,
    float* __restrict__ Cout, int mode) {
    extern __shared__ char smem[];
    const uint32_t sb = smem_u32(smem);
    const int tid = threadIdx.x;
    const int wid = tid >> 5, lane = tid & 31;
    const int wm = wid >> 2, wn = wid & 3;
    const int m0 = blockIdx.x * 128;
    const int nt = blockIdx.y;
    const int n0 = nt * 128;

    const __nv_bfloat16* gsrc[4] = {
        Ah + (size_t)m0 * KDIM, Al + (size_t)m0 * KDIM,
        Bh + (size_t)n0 * KDIM, Bl + (size_t)n0 * KDIM };

    const int crow  = tid >> 1;
    const int chalf = tid & 1;

    const int g    = lane >> 3;
    const int rsub = ((g & 1) << 3) + (lane & 7);
    const int ksubA = (g >> 1) * 8;
    const int rsubB = ((g >> 1) << 3) + (lane & 7);
    const int ksubB = (g & 1) * 8;

    float acc[4][4][4] = {};

    const int NC = KDIM / BK;
    {
        #pragma unroll
        for (int mat = 0; mat < 4; mat++) {
            const __nv_bfloat16* src = gsrc[mat] + (size_t)crow * KDIM + chalf * 16;
            uint32_t dst = sb + mat * MATB + crow * ROWB + chalf * 32;
            cp_async16(dst, src);
            cp_async16(dst + 16, src + 8);
        }
        cp_commit();
    }

    for (int c = 0; c < NC; c++) {
        const int buf = c & 1;
        if (c + 1 < NC) {
            uint32_t sbase = sb + (buf ^ 1) * STAGEB;
            #pragma unroll
            for (int mat = 0; mat < 4; mat++) {
                const __nv_bfloat16* src =
                    gsrc[mat] + (size_t)crow * KDIM + (c + 1) * BK + chalf * 16;
                uint32_t dst = sbase + mat * MATB + crow * ROWB + chalf * 32;
                cp_async16(dst, src);
                cp_async16(dst + 16, src + 8);
            }
            cp_commit();
            cp_wait<1>();
        } else {
            cp_wait<0>();
        }
        __syncthreads();

        const uint32_t stage = sb + buf * STAGEB;
        #pragma unroll
        for (int ks = 0; ks < 2; ks++) {
            uint32_t afr[4][4], bhf[2][4], blf[2][4];
            #pragma unroll
            for (int mt = 0; mt < 4; mt++)
                ldm_x4(afr[mt], stage + 0 * MATB +
                       (wm * 64 + mt * 16 + rsub) * ROWB + (ks * 16 + ksubA) * 2);
            #pragma unroll
            for (int p = 0; p < 2; p++)
                ldm_x4(bhf[p], stage + 2 * MATB +
                       (wn * 32 + p * 16 + rsubB) * ROWB + (ks * 16 + ksubB) * 2);
            #pragma unroll
            for (int mt = 0; mt < 4; mt++)
                #pragma unroll
                for (int n4 = 0; n4 < 4; n4++)
                    mma_bf16(acc[mt][n4], afr[mt], &bhf[n4 >> 1][(n4 & 1) * 2]);
            #pragma unroll
            for (int p = 0; p < 2; p++)
                ldm_x4(blf[p], stage + 3 * MATB +
                       (wn * 32 + p * 16 + rsubB) * ROWB + (ks * 16 + ksubB) * 2);
            #pragma unroll
            for (int mt = 0; mt < 4; mt++)
                #pragma unroll
                for (int n4 = 0; n4 < 4; n4++)
                    mma_bf16(acc[mt][n4], afr[mt], &blf[n4 >> 1][(n4 & 1) * 2]);
            #pragma unroll
            for (int mt = 0; mt < 4; mt++)
                ldm_x4(afr[mt], stage + 1 * MATB +
                       (wm * 64 + mt * 16 + rsub) * ROWB + (ks * 16 + ksubA) * 2);
            #pragma unroll
            for (int mt = 0; mt < 4; mt++)
                #pragma unroll
                for (int n4 = 0; n4 < 4; n4++)
                    mma_bf16(acc[mt][n4], afr[mt], &bhf[n4 >> 1][(n4 & 1) * 2]);
        }
        __syncthreads();
    }

    float* C;
    int Nc, nc0;
    if (mode == 0) {
        if (nt < 8)       { C = g_q; Nc = HID;      nc0 = n0; }
        else if (nt < 10) { C = g_k; Nc = NKV * DH; nc0 = (nt - 8) * 128; }
        else              { C = g_v; Nc = NKV * DH; nc0 = (nt - 10) * 128; }
    } else { C = Cout; Nc = HID; nc0 = n0; }
    const int rbase = m0 + wm * 64 + (lane >> 2);
    const int cbase = nc0 + wn * 32 + (lane & 3) * 2;
    #pragma unroll
    for (int mt = 0; mt < 4; mt++)
        #pragma unroll
        for (int n4 = 0; n4 < 4; n4++) {
            int r = rbase + mt * 16;
            int cc = cbase + n4 * 8;
            *(float2*)(C + (size_t)r * Nc + cc) =
                make_float2(acc[mt][n4][0], acc[mt][n4][1]);
            *(float2*)(C + (size_t)(r + 8) * Nc + cc) =
                make_float2(acc[mt][n4][2], acc[mt][n4][3]);
        }
}

// ---------------------------------------------------------------------------
// Sincos table
// ---------------------------------------------------------------------------
__global__ void sincos_table_kernel(const int* __restrict__ pos_ids) {
    int idx = blockIdx.x * blockDim.x + threadIdx.x;
    if (idx >= SEQ * 32) return;
    int i = idx & 31;
    int s = idx >> 5;
    int pos = pos_ids[s];
    double invf = pow(10000.0, -(double)i / 32.0);
    float ang = (float)((double)pos * invf);
    double sd, cd;
    sincos((double)ang, &sd, &cd);
    g_sc[idx] = make_float2((float)sd, (float)cd);
}

// ---------------------------------------------------------------------------
// Sliding-window attention with fused RoPE (staging) and fused bf16-split
// output (epilogue). Block = (32-query tile, kv head).
// ---------------------------------------------------------------------------
#define ATTN_SMEM ((64 * 97 + 95 * 64 + 128 * 64 + 8 * 4 * 64) * 4)

__global__ __launch_bounds__(256) void attn_kernel(const int* __restrict__ mask) {
    extern __shared__ float smarr[];
    float* kT = smarr;              // [64 d][97]
    float* vS = kT + 64 * 97;       // [95][64]
    float* qs = vS + 95 * 64;       // [128][64]  row r = sl*4 + h
    float* ps = qs + 128 * 64;      // [8 warps][4 h][64]

    const int g  = blockIdx.y;
    const int s0 = blockIdx.x * 32;
    const int tid = threadIdx.x;

    // Stage K (with RoPE) and V. idx over 95 rows x 32 dim-pairs.
    for (int idx = tid; idx < 95 * 32; idx += 256) {
        int j = idx >> 5;
        int d = idx & 31;
        int jg = s0 - 63 + j;
        float r0 = 0.f, r1 = 0.f, v0 = 0.f, v1 = 0.f;
        if (jg >= 0) {
            size_t off = (size_t)jg * (NKV * DH) + g * DH + d;
            float x0 = g_k[off];
            float x1 = g_k[off + 32];
            float2 sc = g_sc[jg * 32 + d];
            r0 = x0 * sc.y - x1 * sc.x;
            r1 = x1 * sc.y + x0 * sc.x;
            v0 = g_v[off];
            v1 = g_v[off + 32];
        }
        kT[d * 97 + j]        = r0;
        kT[(d + 32) * 97 + j] = r1;
        vS[j * 64 + d]        = v0;
        vS[j * 64 + d + 32]   = v1;
    }
    // Stage Q with RoPE. idx over 128 rows x 32 dim-pairs.
    for (int idx = tid; idx < 128 * 32; idx += 256) {
        int r = idx >> 5;
        int d = idx & 31;
        int sl = r >> 2;
        int hl = r & 3;
        int s  = s0 + sl;
        size_t off = (size_t)s * HID + (4 * g + hl) * DH + d;
        float x0 = g_q[off];
        float x1 = g_q[off + 32];
        float2 sc = g_sc[s * 32 + d];
        qs[r * 64 + d]      = x0 * sc.y - x1 * sc.x;
        qs[r * 64 + d + 32] = x1 * sc.y + x0 * sc.x;
    }
    __syncthreads();

    const int warp = tid >> 5;
    const int lane = tid & 31;

    for (int sl_i = 0; sl_i < 4; sl_i++) {
        const int sl = warp * 4 + sl_i;
        const int s  = s0 + sl;
        const int jb = sl;

        float sc0[4] = {}, sc1[4] = {};
        #pragma unroll
        for (int d = 0; d < 64; d++) {
            const float* kr = kT + d * 97 + jb;
            float k0 = kr[lane];
            float k1 = kr[lane + 32];
            #pragma unroll
            for (int h = 0; h < 4; h++) {
                float qd = qs[(sl * 4 + h) * 64 + d];
                sc0[h] += qd * k0;
                sc1[h] += qd * k1;
            }
        }
        const int* mrow = mask + (size_t)s * WIN;
        bool mk0 = mrow[lane] <= 0;
        bool mk1 = mrow[lane + 32] <= 0;

        #pragma unroll
        for (int h = 0; h < 4; h++) {
            float a0 = mk0 ? -1e30f : sc0[h] * 0.125f;
            float a1 = mk1 ? -1e30f : sc1[h] * 0.125f;
            float mx = fmaxf(a0, a1);
            #pragma unroll
            for (int o = 16; o; o >>= 1)
                mx = fmaxf(mx, __shfl_xor_sync(0xffffffffu, mx, o));
            float e0 = __expf(a0 - mx);
            float e1 = __expf(a1 - mx);
            float sum = e0 + e1;
            #pragma unroll
            for (int o = 16; o; o >>= 1)
                sum += __shfl_xor_sync(0xffffffffu, sum, o);
            float inv = 1.f / sum;
            float* pr = ps + (warp * 4 + h) * 64;
            pr[lane]      = e0 * inv;
            pr[lane + 32] = e1 * inv;
        }
        __syncwarp();

        float o0[4] = {}, o1[4] = {};
        const int d0 = lane * 2;
        #pragma unroll
        for (int w = 0; w < 64; w++) {
            float2 vv = *(const float2*)&vS[(jb + w) * 64 + d0];
            #pragma unroll
            for (int h = 0; h < 4; h++) {
                float p = ps[(warp * 4 + h) * 64 + w];
                o0[h] += p * vv.x;
                o1[h] += p * vv.y;
            }
        }
        __syncwarp();

        // Fused bf16 hi/lo split output (feeds O-projection GEMM directly)
        #pragma unroll
        for (int h = 0; h < 4; h++) {
            size_t off = (size_t)s * HID + (4 * g + h) * DH + d0;
            __nv_bfloat16 h0 = __float2bfloat16_rn(o0[h]);
            __nv_bfloat16 h1 = __float2bfloat16_rn(o1[h]);
            __nv_bfloat16 l0 = __float2bfloat16_rn(o0[h] - __bfloat162float(h0));
            __nv_bfloat16 l1 = __float2bfloat16_rn(o1[h] - __bfloat162float(h1));
            *(__nv_bfloat162*)(g_ch + off) = __nv_bfloat162(h0, h1);
            *(__nv_bfloat162*)(g_cl + off) = __nv_bfloat162(l0, l1);
        }
    }
}

// ---------------------------------------------------------------------------
extern "C" void kernel_launch(void* const* d_in, const int* in_sizes, int n_in,
                              void* d_out, int out_size) {
    const float* hidden = (const float*)d_in[0];
    const int*   mask   = (const int*)d_in[1];
    const int*   pos    = (const int*)d_in[2];
    const float* qw     = (const float*)d_in[3];
    const float* kw     = (const float*)d_in[4];
    const float* vw     = (const float*)d_in[5];
    const float* ow     = (const float*)d_in[6];
    float* out = (float*)d_out;

    __nv_bfloat16 *ah, *al, *b1h, *b1l, *b2h, *b2l, *chh, *cll;
    cudaGetSymbolAddress((void**)&ah,  g_ah);
    cudaGetSymbolAddress((void**)&al,  g_al);
    cudaGetSymbolAddress((void**)&b1h, g_b1h);
    cudaGetSymbolAddress((void**)&b1l, g_b1l);
    cudaGetSymbolAddress((void**)&b2h, g_b2h);
    cudaGetSymbolAddress((void**)&b2l, g_b2l);
    cudaGetSymbolAddress((void**)&chh, g_ch);
    cudaGetSymbolAddress((void**)&cll, g_cl);

    cudaFuncSetAttribute(gemm_mma, cudaFuncAttributeMaxDynamicSharedMemorySize,
                         GSMEM);
    cudaFuncSetAttribute(attn_kernel, cudaFuncAttributeMaxDynamicSharedMemorySize,
                         ATTN_SMEM);

    sincos_table_kernel<<<(SEQ * 32 + 255) / 256, 256>>>(pos);

    convert_split<<<(SEQ * KDIM / 4 + 255) / 256, 256>>>(hidden, ah, al,
                                                         SEQ * KDIM / 4);
    convert_wT_all<<<2560, dim3(32, 8)>>>(qw, kw, vw, ow);

    gemm_mma<<<dim3(SEQ / 128, 12), 256, GSMEM>>>(ah, al, b1h, b1l, nullptr, 0);

    attn_kernel<<<dim3(SEQ / 32, NKV), 256, ATTN_SMEM>>>(mask);

    gemm_mma<<<dim3(SEQ / 128, 8), 256, GSMEM>>>(chh, cll, b2h, b2l, out, 1);
}

// round 7
// speedup vs baseline: 3.8052x; 1.0675x over previous
#include <cuda_runtime.h>
#include <cuda_bf16.h>
#include <math.h>
#include <stdint.h>

#define SEQ   2048
#define HID   1024
#define KDIM  1024
#define NH    16
#define NKV   4
#define DH    64
#define WIN   64

// ---------------------------------------------------------------------------
// Scratch (device globals — no allocation allowed)
// ---------------------------------------------------------------------------
__device__ float g_q[SEQ * HID];
__device__ float g_k[SEQ * NKV * DH];
__device__ float g_v[SEQ * NKV * DH];
__device__ float2 g_sc[SEQ * 32];

__device__ __nv_bfloat16 g_ah[SEQ * KDIM],  g_al[SEQ * KDIM];    // hidden split
__device__ __nv_bfloat16 g_b1h[1536 * KDIM], g_b1l[1536 * KDIM]; // qkv W^T split
__device__ __nv_bfloat16 g_b2h[1024 * KDIM], g_b2l[1024 * KDIM]; // o W^T split
__device__ __nv_bfloat16 g_ch[SEQ * KDIM],  g_cl[SEQ * KDIM];    // attn-out split

// ---------------------------------------------------------------------------
// Baseline-PTX async-copy / ldmatrix / mma helpers (sm_80+, legal in compute_103)
// ---------------------------------------------------------------------------
__device__ __forceinline__ uint32_t smem_u32(const void* p) {
    uint32_t a;
    asm("{ .reg .u64 t; cvta.to.shared.u64 t, %1; cvt.u32.u64 %0, t; }"
        : "=r"(a) : "l"(p));
    return a;
}
__device__ __forceinline__ void cp_async16(uint32_t d, const void* s) {
    asm volatile("cp.async.cg.shared.global [%0], [%1], 16;" :: "r"(d), "l"(s));
}
__device__ __forceinline__ void cp_commit() {
    asm volatile("cp.async.commit_group;" ::: "memory");
}
template <int N> __device__ __forceinline__ void cp_wait() {
    asm volatile("cp.async.wait_group %0;" :: "n"(N) : "memory");
}
__device__ __forceinline__ void ldm_x4(uint32_t* r, uint32_t addr) {
    asm volatile("ldmatrix.sync.aligned.m8n8.x4.shared.b16 {%0,%1,%2,%3}, [%4];"
                 : "=r"(r[0]), "=r"(r[1]), "=r"(r[2]), "=r"(r[3]) : "r"(addr));
}
__device__ __forceinline__ void mma_bf16(float* c, const uint32_t* a,
                                         const uint32_t* b) {
    asm volatile("mma.sync.aligned.m16n8k16.row.col.f32.bf16.bf16.f32 "
                 "{%0,%1,%2,%3}, {%4,%5,%6,%7}, {%8,%9}, {%0,%1,%2,%3};"
                 : "+f"(c[0]), "+f"(c[1]), "+f"(c[2]), "+f"(c[3])
                 : "r"(a[0]), "r"(a[1]), "r"(a[2]), "r"(a[3]),
                   "r"(b[0]), "r"(b[1]));
}

// ---------------------------------------------------------------------------
// Conversion kernels (fp32 -> bf16 hi/lo split)
// ---------------------------------------------------------------------------
__global__ void convert_split(const float* __restrict__ x,
                              __nv_bfloat16* __restrict__ hi,
                              __nv_bfloat16* __restrict__ lo, int n4) {
    int i = blockIdx.x * blockDim.x + threadIdx.x;
    if (i >= n4) return;
    float4 v = ((const float4*)x)[i];
    __nv_bfloat16 h0 = __float2bfloat16_rn(v.x);
    __nv_bfloat16 h1 = __float2bfloat16_rn(v.y);
    __nv_bfloat16 h2 = __float2bfloat16_rn(v.z);
    __nv_bfloat16 h3 = __float2bfloat16_rn(v.w);
    __nv_bfloat16 l0 = __float2bfloat16_rn(v.x - __bfloat162float(h0));
    __nv_bfloat16 l1 = __float2bfloat16_rn(v.y - __bfloat162float(h1));
    __nv_bfloat16 l2 = __float2bfloat16_rn(v.z - __bfloat162float(h2));
    __nv_bfloat16 l3 = __float2bfloat16_rn(v.w - __bfloat162float(h3));
    ((__nv_bfloat162*)hi)[i * 2]     = __nv_bfloat162(h0, h1);
    ((__nv_bfloat162*)hi)[i * 2 + 1] = __nv_bfloat162(h2, h3);
    ((__nv_bfloat162*)lo)[i * 2]     = __nv_bfloat162(l0, l1);
    ((__nv_bfloat162*)lo)[i * 2 + 1] = __nv_bfloat162(l2, l3);
}

// Merged transpose+split of all 4 weights: w[K][Nsrc] -> dst[(roff+n)][k]
__global__ void convert_wT_all(const float* __restrict__ qw,
                               const float* __restrict__ kw,
                               const float* __restrict__ vw,
                               const float* __restrict__ ow) {
    __shared__ float t[32][33];
    int b = blockIdx.x;
    const float* w;
    __nv_bfloat16 *th, *tl;
    int Nsrc, roff, local;
    if (b < 1024)      { w = qw; th = g_b1h; tl = g_b1l; Nsrc = 1024; roff = 0;    local = b; }
    else if (b < 1280) { w = kw; th = g_b1h; tl = g_b1l; Nsrc = 256;  roff = 1024; local = b - 1024; }
    else if (b < 1536) { w = vw; th = g_b1h; tl = g_b1l; Nsrc = 256;  roff = 1280; local = b - 1280; }
    else               { w = ow; th = g_b2h; tl = g_b2l; Nsrc = 1024; roff = 0;    local = b - 1536; }
    int ntn = Nsrc / 32;
    int nb = (local % ntn) * 32;
    int kb = (local / ntn) * 32;
    int tx = threadIdx.x, ty = threadIdx.y;   // (32, 8)
    #pragma unroll
    for (int j = 0; j < 32; j += 8)
        t[ty + j][tx] = w[(size_t)(kb + ty + j) * Nsrc + nb + tx];
    __syncthreads();
    #pragma unroll
    for (int j = 0; j < 32; j += 8) {
        float x = t[tx][ty + j];
        __nv_bfloat16 h = __float2bfloat16_rn(x);
        __nv_bfloat16 l = __float2bfloat16_rn(x - __bfloat162float(h));
        size_t o = (size_t)(roff + nb + ty + j) * KDIM + kb + tx;
        th[o] = h;
        tl[o] = l;
    }
}

// ---------------------------------------------------------------------------
// HMMA GEMM: C = A @ B^T, bf16-split 3-term, fp32 accum.
// CTA tile 128x64, K chunks of 32, cp.async double buffer, 8 warps (4x2),
// each warp 32x32 via 2x4 m16n8k16 tiles. 3 CTAs/SM.
// mode 0: qkv demux (blockIdx.y -> g_q/g_k/g_v). mode 1: write Cout.
// ---------------------------------------------------------------------------
#define BK      32
#define ROWB    80
#define AMATB   (128 * ROWB)         // 10240
#define BMATB   (64 * ROWB)          // 5120
#define STAGEB  (2 * AMATB + 2 * BMATB)   // 30720
#define GSMEM   (2 * STAGEB)              // 61440

__global__ __launch_bounds__(256, 3) void gemm_mma(
    const __nv_bfloat16* __restrict__ Ah, const __nv_bfloat16* __restrict__ Al,
    const __nv_bfloat16* __restrict__ Bh, const __nv_bfloat16* __restrict__ Bl,
    float* __restrict__ Cout, int mode) {
    extern __shared__ char smem[];
    const uint32_t sb = smem_u32(smem);
    const int tid = threadIdx.x;
    const int wid = tid >> 5, lane = tid & 31;
    const int wm = wid >> 1, wn = wid & 1;   // 4 x 2 warp grid
    const int m0 = blockIdx.x * 128;
    const int nt = blockIdx.y;
    const int n0 = nt * 64;

    const __nv_bfloat16* gA[2] = { Ah + (size_t)m0 * KDIM, Al + (size_t)m0 * KDIM };
    const __nv_bfloat16* gB[2] = { Bh + (size_t)n0 * KDIM, Bl + (size_t)n0 * KDIM };

    // A loads: 128 rows x 32 cols; thread -> (row, 16B-half)
    const int arow  = tid >> 1;
    const int ahalf = tid & 1;
    // B loads: 64 rows x 32 cols; thread -> (row, 16B-quarter... 4 chunks of 8 bf16)
    const int brow = tid >> 2;
    const int bseg = tid & 3;

    // ldmatrix lane address components
    const int g2    = lane >> 3;
    const int rsub  = ((g2 & 1) << 3) + (lane & 7);
    const int ksubA = (g2 >> 1) * 8;
    const int rsubB = ((g2 >> 1) << 3) + (lane & 7);
    const int ksubB = (g2 & 1) * 8;

    float acc[2][4][4] = {};

    const int NC = KDIM / BK;
    // stage offsets within one buffer: Ahi 0, Alo AMATB, Bhi 2*AMATB, Blo +BMATB
    auto load_stage = [&](int c, int buf) {
        uint32_t base = sb + buf * STAGEB;
        const int kc = c * BK;
        #pragma unroll
        for (int m = 0; m < 2; m++) {
            const __nv_bfloat16* src = gA[m] + (size_t)arow * KDIM + kc + ahalf * 16;
            uint32_t dst = base + m * AMATB + arow * ROWB + ahalf * 32;
            cp_async16(dst, src);
            cp_async16(dst + 16, src + 8);
        }
        #pragma unroll
        for (int m = 0; m < 2; m++) {
            const __nv_bfloat16* src = gB[m] + (size_t)brow * KDIM + kc + bseg * 8;
            uint32_t dst = base + 2 * AMATB + m * BMATB + brow * ROWB + bseg * 16;
            cp_async16(dst, src);
        }
        cp_commit();
    };

    load_stage(0, 0);

    for (int c = 0; c < NC; c++) {
        const int buf = c & 1;
        if (c + 1 < NC) {
            load_stage(c + 1, buf ^ 1);
            cp_wait<1>();
        } else {
            cp_wait<0>();
        }
        __syncthreads();

        const uint32_t stage = sb + buf * STAGEB;
        const uint32_t aBase = stage;
        const uint32_t bBase = stage + 2 * AMATB;
        #pragma unroll
        for (int ks = 0; ks < 2; ks++) {
            uint32_t afr[2][4], bhf[2][4], blf[2][4];
            #pragma unroll
            for (int mt = 0; mt < 2; mt++)
                ldm_x4(afr[mt], aBase +
                       (wm * 32 + mt * 16 + rsub) * ROWB + (ks * 16 + ksubA) * 2);
            #pragma unroll
            for (int p = 0; p < 2; p++)
                ldm_x4(bhf[p], bBase +
                       (wn * 32 + p * 16 + rsubB) * ROWB + (ks * 16 + ksubB) * 2);
            #pragma unroll
            for (int mt = 0; mt < 2; mt++)
                #pragma unroll
                for (int n4 = 0; n4 < 4; n4++)
                    mma_bf16(acc[mt][n4], afr[mt], &bhf[n4 >> 1][(n4 & 1) * 2]);
            #pragma unroll
            for (int p = 0; p < 2; p++)
                ldm_x4(blf[p], bBase + BMATB +
                       (wn * 32 + p * 16 + rsubB) * ROWB + (ks * 16 + ksubB) * 2);
            #pragma unroll
            for (int mt = 0; mt < 2; mt++)
                #pragma unroll
                for (int n4 = 0; n4 < 4; n4++)
                    mma_bf16(acc[mt][n4], afr[mt], &blf[n4 >> 1][(n4 & 1) * 2]);
            #pragma unroll
            for (int mt = 0; mt < 2; mt++)
                ldm_x4(afr[mt], aBase + AMATB +
                       (wm * 32 + mt * 16 + rsub) * ROWB + (ks * 16 + ksubA) * 2);
            #pragma unroll
            for (int mt = 0; mt < 2; mt++)
                #pragma unroll
                for (int n4 = 0; n4 < 4; n4++)
                    mma_bf16(acc[mt][n4], afr[mt], &bhf[n4 >> 1][(n4 & 1) * 2]);
        }
        __syncthreads();
    }

    float* C;
    int Nc, nc0;
    if (mode == 0) {
        if (nt < 16)      { C = g_q; Nc = HID;      nc0 = n0; }
        else if (nt < 20) { C = g_k; Nc = NKV * DH; nc0 = (nt - 16) * 64; }
        else              { C = g_v; Nc = NKV * DH; nc0 = (nt - 20) * 64; }
    } else { C = Cout; Nc = HID; nc0 = n0; }
    const int rbase = m0 + wm * 32 + (lane >> 2);
    const int cbase = nc0 + wn * 32 + (lane & 3) * 2;
    #pragma unroll
    for (int mt = 0; mt < 2; mt++)
        #pragma unroll
        for (int n4 = 0; n4 < 4; n4++) {
            int r = rbase + mt * 16;
            int cc = cbase + n4 * 8;
            *(float2*)(C + (size_t)r * Nc + cc) =
                make_float2(acc[mt][n4][0], acc[mt][n4][1]);
            *(float2*)(C + (size_t)(r + 8) * Nc + cc) =
                make_float2(acc[mt][n4][2], acc[mt][n4][3]);
        }
}

// ---------------------------------------------------------------------------
// Sincos table
// ---------------------------------------------------------------------------
__global__ void sincos_table_kernel(const int* __restrict__ pos_ids) {
    int idx = blockIdx.x * blockDim.x + threadIdx.x;
    if (idx >= SEQ * 32) return;
    int i = idx & 31;
    int s = idx >> 5;
    int pos = pos_ids[s];
    double invf = pow(10000.0, -(double)i / 32.0);
    float ang = (float)((double)pos * invf);
    double sd, cd;
    sincos((double)ang, &sd, &cd);
    g_sc[idx] = make_float2((float)sd, (float)cd);
}

// ---------------------------------------------------------------------------
// Sliding-window attention with fused RoPE (staging) and fused bf16-split
// output (epilogue). Block = (32-query tile, kv head).
// ---------------------------------------------------------------------------
#define ATTN_SMEM ((64 * 97 + 95 * 64 + 128 * 64 + 8 * 4 * 64) * 4)

__global__ __launch_bounds__(256) void attn_kernel(const int* __restrict__ mask) {
    extern __shared__ float smarr[];
    float* kT = smarr;              // [64 d][97]
    float* vS = kT + 64 * 97;       // [95][64]
    float* qs = vS + 95 * 64;       // [128][64]  row r = sl*4 + h
    float* ps = qs + 128 * 64;      // [8 warps][4 h][64]

    const int g  = blockIdx.y;
    const int s0 = blockIdx.x * 32;
    const int tid = threadIdx.x;

    for (int idx = tid; idx < 95 * 32; idx += 256) {
        int j = idx >> 5;
        int d = idx & 31;
        int jg = s0 - 63 + j;
        float r0 = 0.f, r1 = 0.f, v0 = 0.f, v1 = 0.f;
        if (jg >= 0) {
            size_t off = (size_t)jg * (NKV * DH) + g * DH + d;
            float x0 = g_k[off];
            float x1 = g_k[off + 32];
            float2 sc = g_sc[jg * 32 + d];
            r0 = x0 * sc.y - x1 * sc.x;
            r1 = x1 * sc.y + x0 * sc.x;
            v0 = g_v[off];
            v1 = g_v[off + 32];
        }
        kT[d * 97 + j]        = r0;
        kT[(d + 32) * 97 + j] = r1;
        vS[j * 64 + d]        = v0;
        vS[j * 64 + d + 32]   = v1;
    }
    for (int idx = tid; idx < 128 * 32; idx += 256) {
        int r = idx >> 5;
        int d = idx & 31;
        int sl = r >> 2;
        int hl = r & 3;
        int s  = s0 + sl;
        size_t off = (size_t)s * HID + (4 * g + hl) * DH + d;
        float x0 = g_q[off];
        float x1 = g_q[off + 32];
        float2 sc = g_sc[s * 32 + d];
        qs[r * 64 + d]      = x0 * sc.y - x1 * sc.x;
        qs[r * 64 + d + 32] = x1 * sc.y + x0 * sc.x;
    }
    __syncthreads();

    const int warp = tid >> 5;
    const int lane = tid & 31;

    for (int sl_i = 0; sl_i < 4; sl_i++) {
        const int sl = warp * 4 + sl_i;
        const int s  = s0 + sl;
        const int jb = sl;

        float sc0[4] = {}, sc1[4] = {};
        #pragma unroll
        for (int d = 0; d < 64; d++) {
            const float* kr = kT + d * 97 + jb;
            float k0 = kr[lane];
            float k1 = kr[lane + 32];
            #pragma unroll
            for (int h = 0; h < 4; h++) {
                float qd = qs[(sl * 4 + h) * 64 + d];
                sc0[h] += qd * k0;
                sc1[h] += qd * k1;
            }
        }
        const int* mrow = mask + (size_t)s * WIN;
        bool mk0 = mrow[lane] <= 0;
        bool mk1 = mrow[lane + 32] <= 0;

        #pragma unroll
        for (int h = 0; h < 4; h++) {
            float a0 = mk0 ? -1e30f : sc0[h] * 0.125f;
            float a1 = mk1 ? -1e30f : sc1[h] * 0.125f;
            float mx = fmaxf(a0, a1);
            #pragma unroll
            for (int o = 16; o; o >>= 1)
                mx = fmaxf(mx, __shfl_xor_sync(0xffffffffu, mx, o));
            float e0 = __expf(a0 - mx);
            float e1 = __expf(a1 - mx);
            float sum = e0 + e1;
            #pragma unroll
            for (int o = 16; o; o >>= 1)
                sum += __shfl_xor_sync(0xffffffffu, sum, o);
            float inv = 1.f / sum;
            float* pr = ps + (warp * 4 + h) * 64;
            pr[lane]      = e0 * inv;
            pr[lane + 32] = e1 * inv;
        }
        __syncwarp();

        float o0[4] = {}, o1[4] = {};
        const int d0 = lane * 2;
        #pragma unroll
        for (int w = 0; w < 64; w++) {
            float2 vv = *(const float2*)&vS[(jb + w) * 64 + d0];
            #pragma unroll
            for (int h = 0; h < 4; h++) {
                float p = ps[(warp * 4 + h) * 64 + w];
                o0[h] += p * vv.x;
                o1[h] += p * vv.y;
            }
        }
        __syncwarp();

        #pragma unroll
        for (int h = 0; h < 4; h++) {
            size_t off = (size_t)s * HID + (4 * g + h) * DH + d0;
            __nv_bfloat16 h0 = __float2bfloat16_rn(o0[h]);
            __nv_bfloat16 h1 = __float2bfloat16_rn(o1[h]);
            __nv_bfloat16 l0 = __float2bfloat16_rn(o0[h] - __bfloat162float(h0));
            __nv_bfloat16 l1 = __float2bfloat16_rn(o1[h] - __bfloat162float(h1));
            *(__nv_bfloat162*)(g_ch + off) = __nv_bfloat162(h0, h1);
            *(__nv_bfloat162*)(g_cl + off) = __nv_bfloat162(l0, l1);
        }
    }
}

// ---------------------------------------------------------------------------
extern "C" void kernel_launch(void* const* d_in, const int* in_sizes, int n_in,
                              void* d_out, int out_size) {
    const float* hidden = (const float*)d_in[0];
    const int*   mask   = (const int*)d_in[1];
    const int*   pos    = (const int*)d_in[2];
    const float* qw     = (const float*)d_in[3];
    const float* kw     = (const float*)d_in[4];
    const float* vw     = (const float*)d_in[5];
    const float* ow     = (const float*)d_in[6];
    float* out = (float*)d_out;

    __nv_bfloat16 *ah, *al, *b1h, *b1l, *b2h, *b2l, *chh, *cll;
    cudaGetSymbolAddress((void**)&ah,  g_ah);
    cudaGetSymbolAddress((void**)&al,  g_al);
    cudaGetSymbolAddress((void**)&b1h, g_b1h);
    cudaGetSymbolAddress((void**)&b1l, g_b1l);
    cudaGetSymbolAddress((void**)&b2h, g_b2h);
    cudaGetSymbolAddress((void**)&b2l, g_b2l);
    cudaGetSymbolAddress((void**)&chh, g_ch);
    cudaGetSymbolAddress((void**)&cll, g_cl);

    cudaFuncSetAttribute(gemm_mma, cudaFuncAttributeMaxDynamicSharedMemorySize,
                         GSMEM);
    cudaFuncSetAttribute(attn_kernel, cudaFuncAttributeMaxDynamicSharedMemorySize,
                         ATTN_SMEM);

    sincos_table_kernel<<<(SEQ * 32 + 255) / 256, 256>>>(pos);

    convert_split<<<(SEQ * KDIM / 4 + 255) / 256, 256>>>(hidden, ah, al,
                                                         SEQ * KDIM / 4);
    convert_wT_all<<<2560, dim3(32, 8)>>>(qw, kw, vw, ow);

    gemm_mma<<<dim3(SEQ / 128, 24), 256, GSMEM>>>(ah, al, b1h, b1l, nullptr, 0);

    attn_kernel<<<dim3(SEQ / 32, NKV), 256, ATTN_SMEM>>>(mask);

    gemm_mma<<<dim3(SEQ / 128, 16), 256, GSMEM>>>(chh, cll, b2h, b2l, out, 1);
}